// round 1
// baseline (speedup 1.0000x reference)
#include <cuda_runtime.h>
#include <cstdint>
#include <cstdio>

#define B 64
#define T 512
#define F 256
#define C 1024
#define KOUT 256

#define NCTA 128      // recurrent CTAs (all resident on 148 SMs)
#define CW 8          // C / NCTA columns per CTA
#define KT 128        // h k-tile staged in smem
#define WPITCH 1036   // smem pitch (floats) for weight rows, conflict-free
#define HPITCH 132    // smem pitch (floats) for h tile rows

// ---------------- device scratch (no allocations allowed) ----------------
__device__ float g_U [(size_t)T * B * C];   // u_t  = x@u_w^T + u_b      [t][b][c]
__device__ float g_GX[(size_t)T * B * C];   // x-part of g_t (+g_b)      [t][b][c]
__device__ float g_AX[(size_t)T * B * C];   // x-part of a_t             [t][b][c]
__device__ float g_H [(size_t)T * B * C];   // h_t after update          [t][b][c]
__device__ float g_hbuf[2][B * C];          // double-buffered recurrent h
__device__ unsigned g_barcnt;
__device__ unsigned g_bargen;

// ---------------- init: h0 = h + tanh(s), copy s, reset barrier ----------
__global__ void init_kernel(const float* __restrict__ h_in,
                            const float* __restrict__ s,
                            float* __restrict__ out_s) {
    int i = blockIdx.x * blockDim.x + threadIdx.x;
    if (i < B * C) {
        int c = i & (C - 1);
        g_hbuf[0][i] = h_in[i] + tanhf(s[c]);
    }
    if (i < C) out_s[i] = s[i];
    if (i == 0) { g_barcnt = 0u; g_bargen = 0u; }
}

// ---------------- precompute GEMM: [32768,256] x [256,3072] --------------
// grid: (512, 48). by>>4 selects {U, GX, AX}; 64x64 tile, 256 thr, 4x4/thr.
__global__ void __launch_bounds__(256) pre_gemm(
    const float* __restrict__ x,
    const float* __restrict__ u_w, const float* __restrict__ u_b,
    const float* __restrict__ g_w, const float* __restrict__ g_b,
    const float* __restrict__ a_w) {
    __shared__ float xs[16][68];
    __shared__ float ws[16][68];
    const int tid = threadIdx.x;
    const int m0 = blockIdx.x * 64;
    const int by = blockIdx.y;
    const int which = by >> 4;
    const int c0 = (by & 15) * 64;

    const float* wsrc; int rstride; const float* bias;
    if (which == 0)      { wsrc = u_w; rstride = F;     bias = u_b; }
    else if (which == 1) { wsrc = g_w; rstride = F + C; bias = g_b; }
    else                 { wsrc = a_w; rstride = F + C; bias = nullptr; }

    const int tx = tid & 15, ty = tid >> 4;
    const int lr = tid >> 2, lq = tid & 3;
    float acc[4][4] = {};

    for (int k0 = 0; k0 < F; k0 += 16) {
        float4 xa = *(const float4*)(x    + (size_t)(m0 + lr) * F       + k0 + lq * 4);
        float4 wv = *(const float4*)(wsrc + (size_t)(c0 + lr) * rstride + k0 + lq * 4);
        __syncthreads();
        xs[lq*4+0][lr] = xa.x; xs[lq*4+1][lr] = xa.y; xs[lq*4+2][lr] = xa.z; xs[lq*4+3][lr] = xa.w;
        ws[lq*4+0][lr] = wv.x; ws[lq*4+1][lr] = wv.y; ws[lq*4+2][lr] = wv.z; ws[lq*4+3][lr] = wv.w;
        __syncthreads();
#pragma unroll
        for (int k = 0; k < 16; ++k) {
            float4 a4 = *(const float4*)&xs[k][ty * 4];
            float4 b4 = *(const float4*)&ws[k][tx * 4];
            float ar[4] = {a4.x, a4.y, a4.z, a4.w};
            float br[4] = {b4.x, b4.y, b4.z, b4.w};
#pragma unroll
            for (int i = 0; i < 4; ++i)
#pragma unroll
                for (int j = 0; j < 4; ++j)
                    acc[i][j] += ar[i] * br[j];
        }
    }

    float* dst = (which == 0) ? g_U : (which == 1) ? g_GX : g_AX;
#pragma unroll
    for (int i = 0; i < 4; ++i) {
        int m = m0 + ty * 4 + i;
        int t = m % T, b = m / T;              // m = b*T + t (row of x)
        size_t base = ((size_t)t * B + b) * C + c0 + tx * 4;
#pragma unroll
        for (int j = 0; j < 4; ++j) {
            float v = acc[i][j];
            if (bias) v += bias[c0 + tx * 4 + j];
            dst[base + j] = v;
        }
    }
}

// ---------------- persistent recurrent kernel ----------------------------
__global__ void __launch_bounds__(256) rec_kernel(
    const float* __restrict__ n_in, const float* __restrict__ d_in,
    const float* __restrict__ amax_in,
    const float* __restrict__ g_w, const float* __restrict__ a_w,
    float* __restrict__ out_n, float* __restrict__ out_d,
    float* __restrict__ out_h, float* __restrict__ out_amax) {
    extern __shared__ float sm[];
    float* wa = sm;                       // [CW][WPITCH]
    float* wg = sm + CW * WPITCH;         // [CW][WPITCH]
    float* hs = sm + 2 * CW * WPITCH;     // [B][HPITCH]

    const int tid  = threadIdx.x;
    const int cta  = blockIdx.x;
    const int c0   = cta * CW;
    const int ci   = tid & 7;
    const int brow = tid >> 3;            // 0..31
    const int b0   = brow, b1 = brow + 32;
    const int c    = c0 + ci;

    // stage this CTA's weight slices (h-part of a_w, g_w) into smem
    {
        int w = tid >> 5, lane = tid & 31;
        const float* ar = a_w + (size_t)(c0 + w) * (F + C) + F;
        const float* gr = g_w + (size_t)(c0 + w) * (F + C) + F;
        for (int kq = lane; kq < C / 4; kq += 32) {
            float4 av = ((const float4*)ar)[kq];
            float4 gv = ((const float4*)gr)[kq];
            *(float4*)&wa[w * WPITCH + kq * 4] = av;
            *(float4*)&wg[w * WPITCH + kq * 4] = gv;
        }
    }
    float sn0 = n_in[b0 * C + c],   sn1 = n_in[b1 * C + c];
    float sd0 = d_in[b0 * C + c],   sd1 = d_in[b1 * C + c];
    float sa0 = amax_in[b0 * C + c], sa1 = amax_in[b1 * C + c];
    float lh0 = 0.f, lh1 = 0.f;
    __syncthreads();

    unsigned gen = 0;
    for (int t = 0; t < T; ++t) {
        const float* hb = g_hbuf[t & 1];
        float aa0 = 0.f, aa1 = 0.f, gg0 = 0.f, gg1 = 0.f;

        for (int kt = 0; kt < C; kt += KT) {
            __syncthreads();
#pragma unroll
            for (int j = 0; j < 8; ++j) {       // stage h[0:64][kt:kt+128]
                int lin = tid + j * 256;
                int bb = lin >> 5, kq = lin & 31;
                float4 v = *(const float4*)(hb + bb * C + kt + kq * 4);
                *(float4*)&hs[bb * HPITCH + kq * 4] = v;
            }
            __syncthreads();
#pragma unroll 8
            for (int k = 0; k < KT; k += 4) {
                float4 wav = *(const float4*)&wa[ci * WPITCH + kt + k];
                float4 wgv = *(const float4*)&wg[ci * WPITCH + kt + k];
                float4 h0v = *(const float4*)&hs[b0 * HPITCH + k];
                float4 h1v = *(const float4*)&hs[b1 * HPITCH + k];
                aa0 += h0v.x * wav.x; aa1 += h1v.x * wav.x;
                gg0 += h0v.x * wgv.x; gg1 += h1v.x * wgv.x;
                aa0 += h0v.y * wav.y; aa1 += h1v.y * wav.y;
                gg0 += h0v.y * wgv.y; gg1 += h1v.y * wgv.y;
                aa0 += h0v.z * wav.z; aa1 += h1v.z * wav.z;
                gg0 += h0v.z * wgv.z; gg1 += h1v.z * wgv.z;
                aa0 += h0v.w * wav.w; aa1 += h1v.w * wav.w;
                gg0 += h0v.w * wgv.w; gg1 += h1v.w * wgv.w;
            }
        }

        size_t base = (size_t)t * (B * C);
        size_t i0 = base + (size_t)b0 * C + c;
        size_t i1 = base + (size_t)b1 * C + c;
        float at0 = aa0 + g_AX[i0], at1 = aa1 + g_AX[i1];
        float gt0 = gg0 + g_GX[i0], gt1 = gg1 + g_GX[i1];
        float z0 = g_U[i0] * tanhf(gt0), z1 = g_U[i1] * tanhf(gt1);
        float an0 = fmaxf(sa0, at0), an1 = fmaxf(sa1, at1);
        float ed0 = expf(sa0 - an0), ed1 = expf(sa1 - an1);
        float es0 = expf(at0 - an0), es1 = expf(at1 - an1);
        sn0 = sn0 * ed0 + z0 * es0;  sn1 = sn1 * ed1 + z1 * es1;
        sd0 = sd0 * ed0 + es0;       sd1 = sd1 * ed1 + es1;
        lh0 = tanhf(sn0 / sd0);      lh1 = tanhf(sn1 / sd1);
        sa0 = an0;                   sa1 = an1;

        float* hw = g_hbuf[(t + 1) & 1];
        hw[b0 * C + c] = lh0;  hw[b1 * C + c] = lh1;
        g_H[i0] = lh0;         g_H[i1] = lh1;

        // ---- grid barrier (all NCTA CTAs resident; sense = generation) ----
        __threadfence();
        __syncthreads();
        if (tid == 0) {
            unsigned arr = atomicAdd(&g_barcnt, 1u);
            if (arr == NCTA - 1) {
                atomicExch(&g_barcnt, 0u);
                __threadfence();
                atomicAdd(&g_bargen, 1u);
            } else {
                while (*((volatile unsigned*)&g_bargen) <= gen) { __nanosleep(64); }
            }
            __threadfence();
        }
        __syncthreads();
        ++gen;
    }

    out_n[b0 * C + c] = sn0;  out_n[b1 * C + c] = sn1;
    out_d[b0 * C + c] = sd0;  out_d[b1 * C + c] = sd1;
    out_h[b0 * C + c] = lh0;  out_h[b1 * C + c] = lh1;
    out_amax[b0 * C + c] = sa0;  out_amax[b1 * C + c] = sa1;
}

// ---------------- output GEMM: outs = H @ o_w^T + o_b --------------------
// grid: (512, 4). A = g_H [32768,1024] rows m = t*B + b; store to [b][t][k].
__global__ void __launch_bounds__(256) out_gemm(
    const float* __restrict__ o_w, const float* __restrict__ o_b,
    float* __restrict__ outp) {
    __shared__ float as_[16][68];
    __shared__ float bs_[16][68];
    const int tid = threadIdx.x;
    const int m0 = blockIdx.x * 64;
    const int c0 = blockIdx.y * 64;
    const int tx = tid & 15, ty = tid >> 4;
    const int lr = tid >> 2, lq = tid & 3;
    float acc[4][4] = {};

    for (int k0 = 0; k0 < C; k0 += 16) {
        float4 av = *(const float4*)(g_H + (size_t)(m0 + lr) * C + k0 + lq * 4);
        float4 bv = *(const float4*)(o_w + (size_t)(c0 + lr) * C + k0 + lq * 4);
        __syncthreads();
        as_[lq*4+0][lr] = av.x; as_[lq*4+1][lr] = av.y; as_[lq*4+2][lr] = av.z; as_[lq*4+3][lr] = av.w;
        bs_[lq*4+0][lr] = bv.x; bs_[lq*4+1][lr] = bv.y; bs_[lq*4+2][lr] = bv.z; bs_[lq*4+3][lr] = bv.w;
        __syncthreads();
#pragma unroll
        for (int k = 0; k < 16; ++k) {
            float4 a4 = *(const float4*)&as_[k][ty * 4];
            float4 b4 = *(const float4*)&bs_[k][tx * 4];
            float ar[4] = {a4.x, a4.y, a4.z, a4.w};
            float br[4] = {b4.x, b4.y, b4.z, b4.w};
#pragma unroll
            for (int i = 0; i < 4; ++i)
#pragma unroll
                for (int j = 0; j < 4; ++j)
                    acc[i][j] += ar[i] * br[j];
        }
    }
#pragma unroll
    for (int i = 0; i < 4; ++i) {
        int m = m0 + ty * 4 + i;
        int t = m >> 6, b = m & 63;            // m = t*B + b
        size_t base = ((size_t)b * T + t) * KOUT + c0 + tx * 4;
#pragma unroll
        for (int j = 0; j < 4; ++j)
            outp[base + j] = acc[i][j] + o_b[c0 + tx * 4 + j];
    }
}

// ---------------- launch ---------------------------------------------------
extern "C" void kernel_launch(void* const* d_in, const int* in_sizes, int n_in,
                              void* d_out, int out_size) {
    (void)in_sizes; (void)n_in; (void)out_size;
    const float* x      = (const float*)d_in[0];
    const float* s      = (const float*)d_in[1];
    const float* n0     = (const float*)d_in[2];
    const float* d0     = (const float*)d_in[3];
    const float* h0     = (const float*)d_in[4];
    const float* amax0  = (const float*)d_in[5];
    const float* u_w    = (const float*)d_in[6];
    const float* u_b    = (const float*)d_in[7];
    const float* g_w    = (const float*)d_in[8];
    const float* g_b    = (const float*)d_in[9];
    const float* a_w    = (const float*)d_in[10];
    const float* o_w    = (const float*)d_in[11];
    const float* o_b    = (const float*)d_in[12];

    float* out        = (float*)d_out;
    float* out_outs   = out;                                   // [B,T,K]
    float* out_s      = out + (size_t)B * T * KOUT;            // [C]
    float* out_n      = out_s + C;                             // [B,C]
    float* out_d      = out_n + (size_t)B * C;
    float* out_h      = out_d + (size_t)B * C;
    float* out_amax   = out_h + (size_t)B * C;

    const int rec_smem = (2 * CW * WPITCH + B * HPITCH) * (int)sizeof(float);
    cudaFuncSetAttribute(rec_kernel, cudaFuncAttributeMaxDynamicSharedMemorySize, rec_smem);

    init_kernel<<<(B * C + 255) / 256, 256>>>(h0, s, out_s);
    pre_gemm<<<dim3(512, 48), 256>>>(x, u_w, u_b, g_w, g_b, a_w);
    rec_kernel<<<NCTA, 256, rec_smem>>>(n0, d0, amax0, g_w, a_w,
                                        out_n, out_d, out_h, out_amax);
    out_gemm<<<dim3(512, 4), 256>>>(o_w, o_b, out_outs);
}

// round 3
// speedup vs baseline: 1.7382x; 1.7382x over previous
#include <cuda_runtime.h>
#include <cuda_bf16.h>
#include <cstdint>

#define B 64
#define T 512
#define F 256
#define C 1024
#define KOUT 256
#define BC (B * C)
#define WROW (F + C)          // 1280 floats per g_w/a_w row

// ---------------- recurrent kernel config --------------------------------
#define RCTA 64               // persistent CTAs; each owns 16 cells
#define RTHR 256
#define CPC  16               // cells per CTA  (A tile M = 32 = 16 a + 16 g)
#define APITCH 1032           // smem A pitch in bf16 (conflict-free)
#define BPITCH 136            // smem B pitch in bf16 (conflict-free)
#define A_BYTES (64 * APITCH * 2)                  // 132096: rows 0-31 hi, 32-63 lo
#define B_STAGE (2 * 64 * BPITCH * 2)              // 34816: hi tile then lo tile
#define SB_OFF(s) (A_BYTES + (s) * B_STAGE)
#define RED_OFF (A_BYTES + 2 * B_STAGE)            // 201728, 8KB reduce buffer
#define RSMEM (RED_OFF + 8192)                     // 209920 bytes

// ---------------- device scratch -----------------------------------------
__device__ __align__(16) float g_U [(size_t)T * BC];
__device__ __align__(16) float g_GX[(size_t)T * BC];
__device__ __align__(16) float g_AX[(size_t)T * BC];
__device__ __align__(16) float g_H [(size_t)T * BC];
__device__ __align__(16) __nv_bfloat16 g_hbhi[2][BC];   // h hi, double buffered
__device__ __align__(16) __nv_bfloat16 g_hblo[2][BC];   // h lo
__device__ __align__(16) __nv_bfloat16 g_Awhi[RCTA * 32 * C];  // weight hi
__device__ __align__(16) __nv_bfloat16 g_Awlo[RCTA * 32 * C];  // weight lo
__device__ unsigned g_barcnt;
__device__ unsigned g_bargen;

// ---------------- helpers -------------------------------------------------
__device__ __forceinline__ uint32_t smem_u32(const void* p) {
    uint32_t a;
    asm("{ .reg .u64 t; cvta.to.shared.u64 t, %1; cvt.u32.u64 %0, t; }"
        : "=r"(a) : "l"(p));
    return a;
}
__device__ __forceinline__ void cpa16(uint32_t dst, const void* src) {
    asm volatile("cp.async.cg.shared.global [%0], [%1], 16;"
                 :: "r"(dst), "l"(src) : "memory");
}
#define CPA_COMMIT() asm volatile("cp.async.commit_group;" ::: "memory")
#define CPA_WAIT(n)  asm volatile("cp.async.wait_group %0;" :: "n"(n) : "memory")

__device__ __forceinline__ void mma16816(float* d, const uint32_t* a,
                                         const uint32_t* b) {
    asm volatile(
        "mma.sync.aligned.m16n8k16.row.col.f32.bf16.bf16.f32 "
        "{%0,%1,%2,%3},{%4,%5,%6,%7},{%8,%9},{%0,%1,%2,%3};"
        : "+f"(d[0]), "+f"(d[1]), "+f"(d[2]), "+f"(d[3])
        : "r"(a[0]), "r"(a[1]), "r"(a[2]), "r"(a[3]), "r"(b[0]), "r"(b[1]));
}

// ---------------- weight prep: split h-part of a_w/g_w into bf16 hi/lo ----
__global__ void wprep_kernel(const float* __restrict__ g_w,
                             const float* __restrict__ a_w) {
    int idx = blockIdx.x * blockDim.x + threadIdx.x;   // over RCTA*32*C = 2M
    int cta = idx >> 15;
    int r   = (idx >> 10) & 31;
    int k   = idx & 1023;
    int cell = cta * CPC + (r & 15);
    const float* src = (r < 16) ? a_w : g_w;
    float v = src[(size_t)cell * WROW + F + k];
    __nv_bfloat16 hi = __float2bfloat16_rn(v);
    __nv_bfloat16 lo = __float2bfloat16_rn(v - __bfloat162float(hi));
    g_Awhi[idx] = hi;
    g_Awlo[idx] = lo;
}

// ---------------- init: h0 = h + tanh(s), copy s, reset barrier ----------
__global__ void init_kernel(const float* __restrict__ h_in,
                            const float* __restrict__ s,
                            float* __restrict__ out_s) {
    int i = blockIdx.x * blockDim.x + threadIdx.x;
    if (i < BC) {
        int c = i & (C - 1);
        float v = h_in[i] + tanhf(s[c]);
        __nv_bfloat16 hi = __float2bfloat16_rn(v);
        g_hbhi[0][i] = hi;
        g_hblo[0][i] = __float2bfloat16_rn(v - __bfloat162float(hi));
    }
    if (i < C) out_s[i] = s[i];
    if (i == 0) { g_barcnt = 0u; g_bargen = 0u; }
}

// ---------------- precompute GEMM: [32768,256] x [256,3072] --------------
__global__ void __launch_bounds__(256) pre_gemm(
    const float* __restrict__ x,
    const float* __restrict__ u_w, const float* __restrict__ u_b,
    const float* __restrict__ g_w, const float* __restrict__ g_b,
    const float* __restrict__ a_w) {
    __shared__ float xs[16][68];
    __shared__ float ws[16][68];
    const int tid = threadIdx.x;
    const int m0 = blockIdx.x * 64;
    const int by = blockIdx.y;
    const int which = by >> 4;
    const int c0 = (by & 15) * 64;

    const float* wsrc; int rstride; const float* bias;
    if (which == 0)      { wsrc = u_w; rstride = F;    bias = u_b; }
    else if (which == 1) { wsrc = g_w; rstride = WROW; bias = g_b; }
    else                 { wsrc = a_w; rstride = WROW; bias = nullptr; }

    const int tx = tid & 15, ty = tid >> 4;
    const int lr = tid >> 2, lq = tid & 3;
    float acc[4][4] = {};

    for (int k0 = 0; k0 < F; k0 += 16) {
        float4 xa = *(const float4*)(x    + (size_t)(m0 + lr) * F       + k0 + lq * 4);
        float4 wv = *(const float4*)(wsrc + (size_t)(c0 + lr) * rstride + k0 + lq * 4);
        __syncthreads();
        xs[lq*4+0][lr] = xa.x; xs[lq*4+1][lr] = xa.y; xs[lq*4+2][lr] = xa.z; xs[lq*4+3][lr] = xa.w;
        ws[lq*4+0][lr] = wv.x; ws[lq*4+1][lr] = wv.y; ws[lq*4+2][lr] = wv.z; ws[lq*4+3][lr] = wv.w;
        __syncthreads();
#pragma unroll
        for (int k = 0; k < 16; ++k) {
            float4 a4 = *(const float4*)&xs[k][ty * 4];
            float4 b4 = *(const float4*)&ws[k][tx * 4];
            float ar[4] = {a4.x, a4.y, a4.z, a4.w};
            float br[4] = {b4.x, b4.y, b4.z, b4.w};
#pragma unroll
            for (int i = 0; i < 4; ++i)
#pragma unroll
                for (int j = 0; j < 4; ++j)
                    acc[i][j] += ar[i] * br[j];
        }
    }

    float* dst = (which == 0) ? g_U : (which == 1) ? g_GX : g_AX;
#pragma unroll
    for (int i = 0; i < 4; ++i) {
        int m = m0 + ty * 4 + i;
        int t = m % T, b = m / T;              // m = b*T + t (row of x)
        size_t base = ((size_t)t * B + b) * C + c0 + tx * 4;
#pragma unroll
        for (int j = 0; j < 4; ++j) {
            float v = acc[i][j];
            if (bias) v += bias[c0 + tx * 4 + j];
            dst[base + j] = v;
        }
    }
}

// ---------------- persistent recurrent kernel (warp mma, bf16x3) ---------
__global__ void __launch_bounds__(RTHR, 1) rec_kernel(
    const float* __restrict__ n_in, const float* __restrict__ d_in,
    const float* __restrict__ amax_in,
    float* __restrict__ out_n, float* __restrict__ out_d,
    float* __restrict__ out_h, float* __restrict__ out_amax) {
    extern __shared__ char smem[];
    const uint32_t sb = smem_u32(smem);
    __nv_bfloat16* As = (__nv_bfloat16*)smem;
    float* red = (float*)(smem + RED_OFF);

    const int tid   = threadIdx.x;
    const int warp  = tid >> 5;
    const int lane  = tid & 31;
    const int gid   = lane >> 2;
    const int tig   = lane & 3;
    const int wn    = warp & 3;           // n-tile (16 batches)
    const int khalf = warp >> 2;          // k-half within chunk
    const int cta   = blockIdx.x;

    // ---- prologue: weights (hi rows 0-31, lo rows 32-63) into smem ----
    for (int i = tid; i < 64 * 128; i += RTHR) {
        int row = i >> 7, q = i & 127;
        const __nv_bfloat16* src = (row < 32)
            ? g_Awhi + ((size_t)(cta * 32 + row)) * C + q * 8
            : g_Awlo + ((size_t)(cta * 32 + row - 32)) * C + q * 8;
        cpa16(sb + (uint32_t)(row * APITCH + q * 8) * 2, src);
    }
    CPA_COMMIT();

    // ---- per-thread recurrent state: 8 (cell,batch) pairs on warps 0-3 ----
    float sn[8], sd[8], sa[8];
    if (warp < 4) {
#pragma unroll
        for (int p = 0; p < 8; ++p) {
            int nf = p >> 2, cs = (p >> 1) & 1, j = p & 1;
            int b = wn * 16 + nf * 8 + 2 * tig + j;
            int cg = cta * CPC + gid + cs * 8;
            sn[p] = n_in[b * C + cg];
            sd[p] = d_in[b * C + cg];
            sa[p] = amax_in[b * C + cg];
        }
    }

    unsigned gen = 0;
    for (int t = 0; t < T; ++t) {
        const int par = t & 1;
        const __nv_bfloat16* hhi = g_hbhi[par];
        const __nv_bfloat16* hlo = g_hblo[par];

        // prefetch B chunks 0,1
#pragma unroll
        for (int c = 0; c < 2; ++c) {
            for (int i = tid; i < 1024; i += RTHR) {
                int row = i >> 4, q = i & 15;
                uint32_t d0 = sb + SB_OFF(c) + (uint32_t)(row * BPITCH) * 2 + q * 16;
                cpa16(d0,         hhi + row * C + c * 128 + q * 8);
                cpa16(d0 + 17408, hlo + row * C + c * 128 + q * 8);
            }
            CPA_COMMIT();
        }

        float acc[16];
#pragma unroll
        for (int q = 0; q < 16; ++q) acc[q] = 0.f;

#pragma unroll 1
        for (int chunk = 0; chunk < 8; ++chunk) {
            if (chunk < 6) CPA_WAIT(1); else CPA_WAIT(0);
            __syncthreads();
            const char* stg = smem + SB_OFF(chunk & 1);
            const __nv_bfloat16* Bhi = (const __nv_bfloat16*)stg;
            const __nv_bfloat16* Blo = (const __nv_bfloat16*)(stg + 17408);
#pragma unroll
            for (int term = 0; term < 3; ++term) {
                const __nv_bfloat16* Ab = As + (term == 2 ? 32 * APITCH : 0);
                const __nv_bfloat16* Bb = (term == 1) ? Blo : Bhi;
#pragma unroll
                for (int ks = 0; ks < 4; ++ks) {
                    int ka = chunk * 128 + khalf * 64 + ks * 16 + 2 * tig;
                    int kb = khalf * 64 + ks * 16 + 2 * tig;
                    uint32_t a0[4], a1[4], b0[2], b1[2];
                    a0[0] = *(const uint32_t*)(Ab + (gid)      * APITCH + ka);
                    a0[1] = *(const uint32_t*)(Ab + (gid + 8)  * APITCH + ka);
                    a0[2] = *(const uint32_t*)(Ab + (gid)      * APITCH + ka + 8);
                    a0[3] = *(const uint32_t*)(Ab + (gid + 8)  * APITCH + ka + 8);
                    a1[0] = *(const uint32_t*)(Ab + (gid + 16) * APITCH + ka);
                    a1[1] = *(const uint32_t*)(Ab + (gid + 24) * APITCH + ka);
                    a1[2] = *(const uint32_t*)(Ab + (gid + 16) * APITCH + ka + 8);
                    a1[3] = *(const uint32_t*)(Ab + (gid + 24) * APITCH + ka + 8);
                    b0[0] = *(const uint32_t*)(Bb + (wn * 16 + gid)     * BPITCH + kb);
                    b0[1] = *(const uint32_t*)(Bb + (wn * 16 + gid)     * BPITCH + kb + 8);
                    b1[0] = *(const uint32_t*)(Bb + (wn * 16 + 8 + gid) * BPITCH + kb);
                    b1[1] = *(const uint32_t*)(Bb + (wn * 16 + 8 + gid) * BPITCH + kb + 8);
                    mma16816(acc + 0,  a0, b0);
                    mma16816(acc + 4,  a0, b1);
                    mma16816(acc + 8,  a1, b0);
                    mma16816(acc + 12, a1, b1);
                }
            }
            if (chunk < 6) {
                __syncthreads();
                for (int i = tid; i < 1024; i += RTHR) {
                    int row = i >> 4, q = i & 15;
                    uint32_t d0 = sb + SB_OFF(chunk & 1)
                                + (uint32_t)(row * BPITCH) * 2 + q * 16;
                    cpa16(d0,         hhi + row * C + (chunk + 2) * 128 + q * 8);
                    cpa16(d0 + 17408, hlo + row * C + (chunk + 2) * 128 + q * 8);
                }
                CPA_COMMIT();
            }
        }

        // ---- reduce k-halves + online-softmax epilogue --------------------
        const size_t tb = (size_t)t * BC;
        float ax[8], gx[8], ux[8];
        if (warp < 4) {
#pragma unroll
            for (int p = 0; p < 8; ++p) {
                int nf = p >> 2, cs = (p >> 1) & 1, j = p & 1;
                int b = wn * 16 + nf * 8 + 2 * tig + j;
                int cg = cta * CPC + gid + cs * 8;
                size_t idx = tb + (size_t)b * C + cg;
                ax[p] = __ldg(&g_AX[idx]);
                gx[p] = __ldg(&g_GX[idx]);
                ux[p] = __ldg(&g_U[idx]);
            }
        } else {
            float* dst = red + (warp - 4) * 32 + lane;
#pragma unroll
            for (int q = 0; q < 16; ++q) dst[q * 128] = acc[q];
        }
        __syncthreads();
        if (warp < 4) {
            const float* sp = red + warp * 32 + lane;
#pragma unroll
            for (int q = 0; q < 16; ++q) acc[q] += sp[q * 128];
#pragma unroll
            for (int p = 0; p < 8; ++p) {
                int nf = p >> 2, cs = (p >> 1) & 1, j = p & 1;
                int b = wn * 16 + nf * 8 + 2 * tig + j;
                int cg = cta * CPC + gid + cs * 8;
                float a  = acc[nf * 4 + cs * 2 + j];
                float g  = acc[8 + nf * 4 + cs * 2 + j];
                float at = a + ax[p];
                float gt = g + gx[p];
                float z  = ux[p] * tanhf(gt);
                float an = fmaxf(sa[p], at);
                float ed = expf(sa[p] - an);
                float es = expf(at - an);
                sn[p] = sn[p] * ed + z * es;
                sd[p] = sd[p] * ed + es;
                float h = tanhf(sn[p] / sd[p]);
                sa[p] = an;
                g_H[tb + (size_t)b * C + cg] = h;
                __nv_bfloat16 hi = __float2bfloat16_rn(h);
                g_hbhi[par ^ 1][b * C + cg] = hi;
                g_hblo[par ^ 1][b * C + cg] =
                    __float2bfloat16_rn(h - __bfloat162float(hi));
            }
        }

        // ---- grid barrier over RCTA CTAs ---------------------------------
        __threadfence();
        __syncthreads();
        if (tid == 0) {
            unsigned arr = atomicAdd(&g_barcnt, 1u);
            if (arr == RCTA - 1) {
                atomicExch(&g_barcnt, 0u);
                __threadfence();
                atomicAdd(&g_bargen, 1u);
            } else {
                while (*(volatile unsigned*)&g_bargen <= gen) __nanosleep(32);
            }
            __threadfence();
        }
        __syncthreads();
        ++gen;
    }

    if (warp < 4) {
#pragma unroll
        for (int p = 0; p < 8; ++p) {
            int nf = p >> 2, cs = (p >> 1) & 1, j = p & 1;
            int b = wn * 16 + nf * 8 + 2 * tig + j;
            int cg = cta * CPC + gid + cs * 8;
            // h from last buffer write: recompute from state
            out_n[b * C + cg]    = sn[p];
            out_d[b * C + cg]    = sd[p];
            out_h[b * C + cg]    = tanhf(sn[p] / sd[p]);
            out_amax[b * C + cg] = sa[p];
        }
    }
}

// ---------------- output GEMM: outs = H @ o_w^T + o_b --------------------
__global__ void __launch_bounds__(256) out_gemm(
    const float* __restrict__ o_w, const float* __restrict__ o_b,
    float* __restrict__ outp) {
    __shared__ float as_[16][68];
    __shared__ float bs_[16][68];
    const int tid = threadIdx.x;
    const int m0 = blockIdx.x * 64;
    const int c0 = blockIdx.y * 64;
    const int tx = tid & 15, ty = tid >> 4;
    const int lr = tid >> 2, lq = tid & 3;
    float acc[4][4] = {};

    for (int k0 = 0; k0 < C; k0 += 16) {
        float4 av = *(const float4*)(g_H + (size_t)(m0 + lr) * C + k0 + lq * 4);
        float4 bv = *(const float4*)(o_w + (size_t)(c0 + lr) * C + k0 + lq * 4);
        __syncthreads();
        as_[lq*4+0][lr] = av.x; as_[lq*4+1][lr] = av.y; as_[lq*4+2][lr] = av.z; as_[lq*4+3][lr] = av.w;
        bs_[lq*4+0][lr] = bv.x; bs_[lq*4+1][lr] = bv.y; bs_[lq*4+2][lr] = bv.z; bs_[lq*4+3][lr] = bv.w;
        __syncthreads();
#pragma unroll
        for (int k = 0; k < 16; ++k) {
            float4 a4 = *(const float4*)&as_[k][ty * 4];
            float4 b4 = *(const float4*)&bs_[k][tx * 4];
            float ar[4] = {a4.x, a4.y, a4.z, a4.w};
            float br[4] = {b4.x, b4.y, b4.z, b4.w};
#pragma unroll
            for (int i = 0; i < 4; ++i)
#pragma unroll
                for (int j = 0; j < 4; ++j)
                    acc[i][j] += ar[i] * br[j];
        }
    }
#pragma unroll
    for (int i = 0; i < 4; ++i) {
        int m = m0 + ty * 4 + i;
        int t = m >> 6, b = m & 63;            // m = t*B + b
        size_t base = ((size_t)b * T + t) * KOUT + c0 + tx * 4;
#pragma unroll
        for (int j = 0; j < 4; ++j)
            outp[base + j] = acc[i][j] + o_b[c0 + tx * 4 + j];
    }
}

// ---------------- launch ---------------------------------------------------
extern "C" void kernel_launch(void* const* d_in, const int* in_sizes, int n_in,
                              void* d_out, int out_size) {
    (void)in_sizes; (void)n_in; (void)out_size;
    const float* x      = (const float*)d_in[0];
    const float* s      = (const float*)d_in[1];
    const float* n0     = (const float*)d_in[2];
    const float* d0     = (const float*)d_in[3];
    const float* h0     = (const float*)d_in[4];
    const float* amax0  = (const float*)d_in[5];
    const float* u_w    = (const float*)d_in[6];
    const float* u_b    = (const float*)d_in[7];
    const float* g_w    = (const float*)d_in[8];
    const float* g_b    = (const float*)d_in[9];
    const float* a_w    = (const float*)d_in[10];
    const float* o_w    = (const float*)d_in[11];
    const float* o_b    = (const float*)d_in[12];

    float* out        = (float*)d_out;
    float* out_outs   = out;                                   // [B,T,K]
    float* out_s      = out + (size_t)B * T * KOUT;            // [C]
    float* out_n      = out_s + C;                             // [B,C]
    float* out_d      = out_n + (size_t)B * C;
    float* out_h      = out_d + (size_t)B * C;
    float* out_amax   = out_h + (size_t)B * C;

    cudaFuncSetAttribute(rec_kernel, cudaFuncAttributeMaxDynamicSharedMemorySize, RSMEM);

    wprep_kernel<<<RCTA * 32 * C / 256, 256>>>(g_w, a_w);
    init_kernel<<<(BC + 255) / 256, 256>>>(h0, s, out_s);
    pre_gemm<<<dim3(512, 48), 256>>>(x, u_w, u_b, g_w, g_b, a_w);
    rec_kernel<<<RCTA, RTHR, RSMEM>>>(n0, d0, amax0,
                                      out_n, out_d, out_h, out_amax);
    out_gemm<<<dim3(512, 4), 256>>>(o_w, o_b, out_outs);
}

// round 4
// speedup vs baseline: 2.0926x; 1.2039x over previous
#include <cuda_runtime.h>
#include <cuda_bf16.h>
#include <cstdint>

#define B 64
#define T 512
#define F 256
#define C 1024
#define KOUT 256
#define BC (B * C)
#define WROW (F + C)          // 1280 floats per g_w/a_w row

// ---------------- recurrent kernel config --------------------------------
#define RCTA 128              // (cg 0..63) x (batch-half 0..1)
#define NCG  64               // cell groups
#define RTHR 256
#define CPC  16               // cells per CTA  (A tile M = 32 = 16 a + 16 g)
#define NB   32               // batches per CTA
#define APITCH 1032           // smem A pitch (bf16), row stride 2064B: conflict-free
#define BPITCH 136            // smem B pitch (bf16), row stride 272B: conflict-free
#define A_BYTES (64 * APITCH * 2)              // 132096: rows 0-31 hi, 32-63 lo
#define B_HALF  (NB * BPITCH * 2)              // 8704 per hi or lo tile
#define B_STAGE (2 * B_HALF)                   // 17408
#define SB_OFF(s) (A_BYTES + (s) * B_STAGE)
#define RED_OFF (A_BYTES + 2 * B_STAGE)        // 166912
#define RSMEM (RED_OFF + 4096)                 // 171008 bytes

// ---------------- device scratch -----------------------------------------
__device__ __align__(16) float g_U [(size_t)T * BC];
__device__ __align__(16) float g_GX[(size_t)T * BC];
__device__ __align__(16) float g_AX[(size_t)T * BC];
__device__ __align__(16) float g_H [(size_t)T * BC];
__device__ __align__(16) __nv_bfloat16 g_hbhi[2][BC];   // h hi, double buffered
__device__ __align__(16) __nv_bfloat16 g_hblo[2][BC];   // h lo
__device__ __align__(16) __nv_bfloat16 g_Awhi[NCG * 32 * C];  // weight hi
__device__ __align__(16) __nv_bfloat16 g_Awlo[NCG * 32 * C];  // weight lo
__device__ unsigned g_barcnt;
__device__ unsigned g_bargen;

// ---------------- helpers -------------------------------------------------
__device__ __forceinline__ uint32_t smem_u32(const void* p) {
    uint32_t a;
    asm("{ .reg .u64 t; cvta.to.shared.u64 t, %1; cvt.u32.u64 %0, t; }"
        : "=r"(a) : "l"(p));
    return a;
}
__device__ __forceinline__ void cpa16(uint32_t dst, const void* src) {
    asm volatile("cp.async.cg.shared.global [%0], [%1], 16;"
                 :: "r"(dst), "l"(src) : "memory");
}
#define CPA_COMMIT() asm volatile("cp.async.commit_group;" ::: "memory")
#define CPA_WAIT(n)  asm volatile("cp.async.wait_group %0;" :: "n"(n) : "memory")

__device__ __forceinline__ void mma16816(float* d, const uint32_t* a,
                                         const uint32_t* b) {
    asm volatile(
        "mma.sync.aligned.m16n8k16.row.col.f32.bf16.bf16.f32 "
        "{%0,%1,%2,%3},{%4,%5,%6,%7},{%8,%9},{%0,%1,%2,%3};"
        : "+f"(d[0]), "+f"(d[1]), "+f"(d[2]), "+f"(d[3])
        : "r"(a[0]), "r"(a[1]), "r"(a[2]), "r"(a[3]), "r"(b[0]), "r"(b[1]));
}
__device__ __forceinline__ void ldm_x4(uint32_t* r, uint32_t a) {
    asm volatile("ldmatrix.sync.aligned.m8n8.x4.shared.b16 {%0,%1,%2,%3}, [%4];"
                 : "=r"(r[0]), "=r"(r[1]), "=r"(r[2]), "=r"(r[3]) : "r"(a));
}
__device__ __forceinline__ void ldm_x2(uint32_t* r, uint32_t a) {
    asm volatile("ldmatrix.sync.aligned.m8n8.x2.shared.b16 {%0,%1}, [%2];"
                 : "=r"(r[0]), "=r"(r[1]) : "r"(a));
}

// ---------------- weight prep: split h-part of a_w/g_w into bf16 hi/lo ----
__global__ void wprep_kernel(const float* __restrict__ g_w,
                             const float* __restrict__ a_w) {
    int idx = blockIdx.x * blockDim.x + threadIdx.x;   // over NCG*32*C = 2M
    int cg  = idx >> 15;
    int r   = (idx >> 10) & 31;
    int k   = idx & 1023;
    int cell = cg * CPC + (r & 15);
    const float* src = (r < 16) ? a_w : g_w;
    float v = src[(size_t)cell * WROW + F + k];
    __nv_bfloat16 hi = __float2bfloat16_rn(v);
    __nv_bfloat16 lo = __float2bfloat16_rn(v - __bfloat162float(hi));
    g_Awhi[idx] = hi;
    g_Awlo[idx] = lo;
}

// ---------------- init: h0 = h + tanh(s), copy s, reset barrier ----------
__global__ void init_kernel(const float* __restrict__ h_in,
                            const float* __restrict__ s,
                            float* __restrict__ out_s) {
    int i = blockIdx.x * blockDim.x + threadIdx.x;
    if (i < BC) {
        int c = i & (C - 1);
        float v = h_in[i] + tanhf(s[c]);
        __nv_bfloat16 hi = __float2bfloat16_rn(v);
        g_hbhi[0][i] = hi;
        g_hblo[0][i] = __float2bfloat16_rn(v - __bfloat162float(hi));
    }
    if (i < C) out_s[i] = s[i];
    if (i == 0) { g_barcnt = 0u; g_bargen = 0u; }
}

// ---------------- precompute GEMM: [32768,256] x [256,3072] --------------
__global__ void __launch_bounds__(256) pre_gemm(
    const float* __restrict__ x,
    const float* __restrict__ u_w, const float* __restrict__ u_b,
    const float* __restrict__ g_w, const float* __restrict__ g_b,
    const float* __restrict__ a_w) {
    __shared__ float xs[16][68];
    __shared__ float ws[16][68];
    const int tid = threadIdx.x;
    const int m0 = blockIdx.x * 64;
    const int by = blockIdx.y;
    const int which = by >> 4;
    const int c0 = (by & 15) * 64;

    const float* wsrc; int rstride; const float* bias;
    if (which == 0)      { wsrc = u_w; rstride = F;    bias = u_b; }
    else if (which == 1) { wsrc = g_w; rstride = WROW; bias = g_b; }
    else                 { wsrc = a_w; rstride = WROW; bias = nullptr; }

    const int tx = tid & 15, ty = tid >> 4;
    const int lr = tid >> 2, lq = tid & 3;
    float acc[4][4] = {};

    for (int k0 = 0; k0 < F; k0 += 16) {
        float4 xa = *(const float4*)(x    + (size_t)(m0 + lr) * F       + k0 + lq * 4);
        float4 wv = *(const float4*)(wsrc + (size_t)(c0 + lr) * rstride + k0 + lq * 4);
        __syncthreads();
        xs[lq*4+0][lr] = xa.x; xs[lq*4+1][lr] = xa.y; xs[lq*4+2][lr] = xa.z; xs[lq*4+3][lr] = xa.w;
        ws[lq*4+0][lr] = wv.x; ws[lq*4+1][lr] = wv.y; ws[lq*4+2][lr] = wv.z; ws[lq*4+3][lr] = wv.w;
        __syncthreads();
#pragma unroll
        for (int k = 0; k < 16; ++k) {
            float4 a4 = *(const float4*)&xs[k][ty * 4];
            float4 b4 = *(const float4*)&ws[k][tx * 4];
            float ar[4] = {a4.x, a4.y, a4.z, a4.w};
            float br[4] = {b4.x, b4.y, b4.z, b4.w};
#pragma unroll
            for (int i = 0; i < 4; ++i)
#pragma unroll
                for (int j = 0; j < 4; ++j)
                    acc[i][j] += ar[i] * br[j];
        }
    }

    float* dst = (which == 0) ? g_U : (which == 1) ? g_GX : g_AX;
#pragma unroll
    for (int i = 0; i < 4; ++i) {
        int m = m0 + ty * 4 + i;
        int t = m % T, b = m / T;              // m = b*T + t (row of x)
        size_t base = ((size_t)t * B + b) * C + c0 + tx * 4;
#pragma unroll
        for (int j = 0; j < 4; ++j) {
            float v = acc[i][j];
            if (bias) v += bias[c0 + tx * 4 + j];
            dst[base + j] = v;
        }
    }
}

// ---------------- persistent recurrent kernel (warp mma + ldmatrix) ------
__global__ void __launch_bounds__(RTHR, 1) rec_kernel(
    const float* __restrict__ n_in, const float* __restrict__ d_in,
    const float* __restrict__ amax_in,
    float* __restrict__ out_n, float* __restrict__ out_d,
    float* __restrict__ out_h, float* __restrict__ out_amax) {
    extern __shared__ char smem[];
    const uint32_t sb = smem_u32(smem);
    float* red = (float*)(smem + RED_OFF);

    const int tid   = threadIdx.x;
    const int warp  = tid >> 5;
    const int lane  = tid & 31;
    const int gid   = lane >> 2;
    const int tig   = lane & 3;
    const int wn    = warp & 3;           // n-tile: batches wn*8..wn*8+7 (local)
    const int khalf = warp >> 2;          // k-half within 128-k chunk
    const int cg    = blockIdx.x >> 1;    // cell group
    const int bh    = blockIdx.x & 1;     // batch half
    const int bbase = bh * NB;

    // ---- prologue: weights (hi rows 0-31, lo rows 32-63) into smem ----
    for (int i = tid; i < 64 * 128; i += RTHR) {
        int row = i >> 7, q = i & 127;
        const __nv_bfloat16* src = (row < 32)
            ? g_Awhi + ((size_t)cg * 32 + row) * C + q * 8
            : g_Awlo + ((size_t)cg * 32 + row - 32) * C + q * 8;
        cpa16(sb + (uint32_t)(row * APITCH + q * 8) * 2, src);
    }
    CPA_COMMIT();

    // ---- ldmatrix lane address components ----
    const int aRow = ((lane >> 3) & 1) * 8 + (lane & 7);
    const int aCol = ((lane >> 4) & 1) * 8;
    // A bases (bytes): [term hi/lo][mtile 0/1]; k offset added per iter
    const uint32_t aHi0 = sb + (uint32_t)((aRow)      * APITCH + aCol) * 2;
    const uint32_t aHi1 = sb + (uint32_t)((16 + aRow) * APITCH + aCol) * 2;
    const uint32_t aLo0 = sb + (uint32_t)((32 + aRow) * APITCH + aCol) * 2;
    const uint32_t aLo1 = sb + (uint32_t)((48 + aRow) * APITCH + aCol) * 2;
    const int bRow = wn * 8 + (lane & 7);
    const int bCol = ((lane >> 3) & 1) * 8;
    const uint32_t bOffB = (uint32_t)(bRow * BPITCH + bCol) * 2;  // + stage + kb*2

    // ---- per-thread recurrent state: 4 (cell,batch) pairs, warps 0-3 ----
    // pair p: cell = cg*16 + gid + (p>>1)*8 ; batch = bbase + wn*8 + 2*tig + (p&1)
    float sn[4], sd[4], sa[4];
    if (khalf == 0) {
#pragma unroll
        for (int p = 0; p < 4; ++p) {
            int b  = bbase + wn * 8 + 2 * tig + (p & 1);
            int cc = cg * CPC + gid + (p >> 1) * 8;
            sn[p] = n_in[b * C + cc];
            sd[p] = d_in[b * C + cc];
            sa[p] = amax_in[b * C + cc];
        }
    }

    unsigned gen = 0;
    for (int t = 0; t < T; ++t) {
        const int par = t & 1;
        const __nv_bfloat16* hhi = g_hbhi[par];
        const __nv_bfloat16* hlo = g_hblo[par];

        // prefetch B chunks 0,1 (rows = this CTA's 32 batches)
#pragma unroll
        for (int ch = 0; ch < 2; ++ch) {
#pragma unroll
            for (int i2 = 0; i2 < 2; ++i2) {
                int i = tid + i2 * RTHR;           // 0..511
                int row = i >> 4, q = i & 15;
                uint32_t d0 = sb + SB_OFF(ch) + (uint32_t)(row * BPITCH) * 2 + q * 16;
                const __nv_bfloat16* s0 = hhi + (size_t)(bbase + row) * C + ch * 128 + q * 8;
                const __nv_bfloat16* s1 = hlo + (size_t)(bbase + row) * C + ch * 128 + q * 8;
                cpa16(d0, s0);
                cpa16(d0 + B_HALF, s1);
            }
            CPA_COMMIT();
        }

        float acc[8];
#pragma unroll
        for (int q = 0; q < 8; ++q) acc[q] = 0.f;

#pragma unroll 1
        for (int chunk = 0; chunk < 8; ++chunk) {
            if (chunk < 6) CPA_WAIT(1); else CPA_WAIT(0);
            __syncthreads();
            const uint32_t stg = sb + SB_OFF(chunk & 1);
#pragma unroll
            for (int ks = 0; ks < 4; ++ks) {
                const int ka = chunk * 128 + khalf * 64 + ks * 16;   // A k index
                const int kb = khalf * 64 + ks * 16;                 // B k in chunk
                uint32_t ah0[4], ah1[4], al0[4], al1[4], bhf[2], blf[2];
                ldm_x4(ah0, aHi0 + ka * 2);
                ldm_x4(ah1, aHi1 + ka * 2);
                ldm_x2(bhf, stg + bOffB + kb * 2);
                ldm_x4(al0, aLo0 + ka * 2);
                ldm_x4(al1, aLo1 + ka * 2);
                ldm_x2(blf, stg + B_HALF + bOffB + kb * 2);
                mma16816(acc + 0, ah0, bhf);
                mma16816(acc + 4, ah1, bhf);
                mma16816(acc + 0, ah0, blf);
                mma16816(acc + 4, ah1, blf);
                mma16816(acc + 0, al0, bhf);
                mma16816(acc + 4, al1, bhf);
            }
            if (chunk < 6) {
                __syncthreads();
#pragma unroll
                for (int i2 = 0; i2 < 2; ++i2) {
                    int i = tid + i2 * RTHR;
                    int row = i >> 4, q = i & 15;
                    uint32_t d0 = sb + SB_OFF(chunk & 1)
                                + (uint32_t)(row * BPITCH) * 2 + q * 16;
                    const __nv_bfloat16* s0 = hhi + (size_t)(bbase + row) * C
                                            + (chunk + 2) * 128 + q * 8;
                    const __nv_bfloat16* s1 = hlo + (size_t)(bbase + row) * C
                                            + (chunk + 2) * 128 + q * 8;
                    cpa16(d0, s0);
                    cpa16(d0 + B_HALF, s1);
                }
                CPA_COMMIT();
            }
        }

        // ---- reduce k-halves + online-softmax epilogue --------------------
        const size_t tb = (size_t)t * BC;
        float ax[4], gx[4], ux[4];
        if (khalf == 0) {
#pragma unroll
            for (int p = 0; p < 4; ++p) {
                int b  = bbase + wn * 8 + 2 * tig + (p & 1);
                int cc = cg * CPC + gid + (p >> 1) * 8;
                size_t idx = tb + (size_t)b * C + cc;
                ax[p] = __ldg(&g_AX[idx]);
                gx[p] = __ldg(&g_GX[idx]);
                ux[p] = __ldg(&g_U[idx]);
            }
        } else {
            float* dst = red + wn * 32 + lane;
#pragma unroll
            for (int q = 0; q < 8; ++q) dst[q * 128] = acc[q];
        }
        __syncthreads();
        if (khalf == 0) {
            const float* sp = red + wn * 32 + lane;
#pragma unroll
            for (int q = 0; q < 8; ++q) acc[q] += sp[q * 128];
#pragma unroll
            for (int p = 0; p < 4; ++p) {
                int b  = bbase + wn * 8 + 2 * tig + (p & 1);
                int cc = cg * CPC + gid + (p >> 1) * 8;
                float at = acc[p] + ax[p];          // acc[0..3] = a rows
                float gt = acc[4 + p] + gx[p];      // acc[4..7] = g rows
                float z  = ux[p] * tanhf(gt);
                float an = fmaxf(sa[p], at);
                float ed = expf(sa[p] - an);
                float es = expf(at - an);
                sn[p] = sn[p] * ed + z * es;
                sd[p] = sd[p] * ed + es;
                float h = tanhf(sn[p] / sd[p]);
                sa[p] = an;
                g_H[tb + (size_t)b * C + cc] = h;
                __nv_bfloat16 hi = __float2bfloat16_rn(h);
                g_hbhi[par ^ 1][b * C + cc] = hi;
                g_hblo[par ^ 1][b * C + cc] =
                    __float2bfloat16_rn(h - __bfloat162float(hi));
            }
        }

        // ---- grid barrier over RCTA CTAs ---------------------------------
        __threadfence();
        __syncthreads();
        if (tid == 0) {
            unsigned arr = atomicAdd(&g_barcnt, 1u);
            if (arr == RCTA - 1) {
                atomicExch(&g_barcnt, 0u);
                __threadfence();
                atomicAdd(&g_bargen, 1u);
            } else {
                while (*(volatile unsigned*)&g_bargen <= gen) __nanosleep(32);
            }
            __threadfence();
        }
        __syncthreads();
        ++gen;
    }

    if (khalf == 0) {
#pragma unroll
        for (int p = 0; p < 4; ++p) {
            int b  = bbase + wn * 8 + 2 * tig + (p & 1);
            int cc = cg * CPC + gid + (p >> 1) * 8;
            out_n[b * C + cc]    = sn[p];
            out_d[b * C + cc]    = sd[p];
            out_h[b * C + cc]    = tanhf(sn[p] / sd[p]);
            out_amax[b * C + cc] = sa[p];
        }
    }
}

// ---------------- output GEMM: outs = H @ o_w^T + o_b --------------------
__global__ void __launch_bounds__(256) out_gemm(
    const float* __restrict__ o_w, const float* __restrict__ o_b,
    float* __restrict__ outp) {
    __shared__ float as_[16][68];
    __shared__ float bs_[16][68];
    const int tid = threadIdx.x;
    const int m0 = blockIdx.x * 64;
    const int c0 = blockIdx.y * 64;
    const int tx = tid & 15, ty = tid >> 4;
    const int lr = tid >> 2, lq = tid & 3;
    float acc[4][4] = {};

    for (int k0 = 0; k0 < C; k0 += 16) {
        float4 av = *(const float4*)(g_H + (size_t)(m0 + lr) * C + k0 + lq * 4);
        float4 bv = *(const float4*)(o_w + (size_t)(c0 + lr) * C + k0 + lq * 4);
        __syncthreads();
        as_[lq*4+0][lr] = av.x; as_[lq*4+1][lr] = av.y; as_[lq*4+2][lr] = av.z; as_[lq*4+3][lr] = av.w;
        bs_[lq*4+0][lr] = bv.x; bs_[lq*4+1][lr] = bv.y; bs_[lq*4+2][lr] = bv.z; bs_[lq*4+3][lr] = bv.w;
        __syncthreads();
#pragma unroll
        for (int k = 0; k < 16; ++k) {
            float4 a4 = *(const float4*)&as_[k][ty * 4];
            float4 b4 = *(const float4*)&bs_[k][tx * 4];
            float ar[4] = {a4.x, a4.y, a4.z, a4.w};
            float br[4] = {b4.x, b4.y, b4.z, b4.w};
#pragma unroll
            for (int i = 0; i < 4; ++i)
#pragma unroll
                for (int j = 0; j < 4; ++j)
                    acc[i][j] += ar[i] * br[j];
        }
    }
#pragma unroll
    for (int i = 0; i < 4; ++i) {
        int m = m0 + ty * 4 + i;
        int t = m >> 6, b = m & 63;            // m = t*B + b
        size_t base = ((size_t)b * T + t) * KOUT + c0 + tx * 4;
#pragma unroll
        for (int j = 0; j < 4; ++j)
            outp[base + j] = acc[i][j] + o_b[c0 + tx * 4 + j];
    }
}

// ---------------- launch ---------------------------------------------------
extern "C" void kernel_launch(void* const* d_in, const int* in_sizes, int n_in,
                              void* d_out, int out_size) {
    (void)in_sizes; (void)n_in; (void)out_size;
    const float* x      = (const float*)d_in[0];
    const float* s      = (const float*)d_in[1];
    const float* n0     = (const float*)d_in[2];
    const float* d0     = (const float*)d_in[3];
    const float* h0     = (const float*)d_in[4];
    const float* amax0  = (const float*)d_in[5];
    const float* u_w    = (const float*)d_in[6];
    const float* u_b    = (const float*)d_in[7];
    const float* g_w    = (const float*)d_in[8];
    const float* g_b    = (const float*)d_in[9];
    const float* a_w    = (const float*)d_in[10];
    const float* o_w    = (const float*)d_in[11];
    const float* o_b    = (const float*)d_in[12];

    float* out        = (float*)d_out;
    float* out_outs   = out;                                   // [B,T,K]
    float* out_s      = out + (size_t)B * T * KOUT;            // [C]
    float* out_n      = out_s + C;                             // [B,C]
    float* out_d      = out_n + (size_t)B * C;
    float* out_h      = out_d + (size_t)B * C;
    float* out_amax   = out_h + (size_t)B * C;

    cudaFuncSetAttribute(rec_kernel, cudaFuncAttributeMaxDynamicSharedMemorySize, RSMEM);

    wprep_kernel<<<NCG * 32 * C / 256, 256>>>(g_w, a_w);
    init_kernel<<<(BC + 255) / 256, 256>>>(h0, s, out_s);
    pre_gemm<<<dim3(512, 48), 256>>>(x, u_w, u_b, g_w, g_b, a_w);
    rec_kernel<<<RCTA, RTHR, RSMEM>>>(n0, d0, amax0,
                                      out_n, out_d, out_h, out_amax);
    out_gemm<<<dim3(512, 4), 256>>>(o_w, o_b, out_outs);
}